// round 1
// baseline (speedup 1.0000x reference)
#include <cuda_runtime.h>
#include <cstdint>
#include <cstddef>

#define E_DIM  1024
#define NHEAD  16
#define HDIM   64
#define BATCH  2
#define SEQ_Q  1024
#define SEQ_KV 4096
#define LN_EPS 1e-5f

// ---------------- scratch (no allocations allowed) ----------------
__device__ float g_Qp[(size_t)BATCH * NHEAD * SEQ_Q * HDIM];     // [B,H,SQ,D]
__device__ float g_Kp[(size_t)BATCH * NHEAD * SEQ_KV * HDIM];    // [B,H,SKV,D]
__device__ float g_Vp[(size_t)BATCH * NHEAD * SEQ_KV * HDIM];    // [B,H,SKV,D]
__device__ float g_attn[(size_t)BATCH * SEQ_Q * E_DIM];          // [B*SQ, E]
__device__ float g_proj[(size_t)BATCH * SEQ_Q * E_DIM];          // [B*SQ, E]

// ---------------- helpers ----------------
__device__ __forceinline__ unsigned f2tf(float f) {
    unsigned u;
    asm("cvt.rna.tf32.f32 %0, %1;" : "=r"(u) : "f"(f));
    return u;
}

__device__ __forceinline__ void mma8(float* c, const unsigned* a, unsigned b0, unsigned b1) {
    asm volatile(
        "mma.sync.aligned.m16n8k8.row.col.f32.tf32.tf32.f32 "
        "{%0,%1,%2,%3}, {%4,%5,%6,%7}, {%8,%9}, {%0,%1,%2,%3};\n"
        : "+f"(c[0]), "+f"(c[1]), "+f"(c[2]), "+f"(c[3])
        : "r"(a[0]), "r"(a[1]), "r"(a[2]), "r"(a[3]), "r"(b0), "r"(b1));
}

// ---------------- GEMM: C[M,N] = A[M,K] * W[N,K]^T + bias ----------------
// K = N = E_DIM. If PERM, output goes to [B, H, S, D] layout (row m = b*S+s, col n = h*64+d).
template <bool PERM>
__device__ __forceinline__ void storeC(float* __restrict__ C, int r, int c, float2 v, int S) {
    if (PERM) {
        int b = r / S;
        int s = r - b * S;
        int h = c >> 6;
        int d = c & 63;
        *(float2*)(C + (((size_t)b * NHEAD + h) * S + s) * HDIM + d) = v;
    } else {
        *(float2*)(C + (size_t)r * E_DIM + c) = v;
    }
}

template <bool PERM>
__global__ void __launch_bounds__(256) gemm_tf32_kernel(
    const float* __restrict__ A, const float* __restrict__ W,
    const float* __restrict__ bias, float* __restrict__ C,
    int M, int S, float outScale)
{
    __shared__ unsigned As[128][36];
    __shared__ unsigned Bs[128][36];

    const int tid  = threadIdx.x;
    const int lane = tid & 31;
    const int warp = tid >> 5;
    const int lq   = lane >> 2;   // group id
    const int kq   = lane & 3;    // thread-in-group
    const int bm   = blockIdx.x * 128;
    const int bn   = blockIdx.y * 128;
    const int wm   = (warp & 3) * 32;   // 4 warps along M
    const int wn   = (warp >> 2) * 64;  // 2 warps along N

    float acc[2][8][4];
#pragma unroll
    for (int mt = 0; mt < 2; mt++)
#pragma unroll
        for (int nt = 0; nt < 8; nt++)
#pragma unroll
            for (int r = 0; r < 4; r++) acc[mt][nt][r] = 0.0f;

    for (int kt = 0; kt < E_DIM / 32; kt++) {
#pragma unroll
        for (int p = 0; p < 4; p++) {
            int i4  = p * 256 + tid;     // 0..1023 float4 slots (128x32 tile)
            int row = i4 >> 3;
            int c4  = i4 & 7;
            float4 va = *(const float4*)(A + (size_t)(bm + row) * E_DIM + kt * 32 + c4 * 4);
            unsigned* da = &As[row][c4 * 4];
            da[0] = f2tf(va.x); da[1] = f2tf(va.y); da[2] = f2tf(va.z); da[3] = f2tf(va.w);
            float4 vb = *(const float4*)(W + (size_t)(bn + row) * E_DIM + kt * 32 + c4 * 4);
            unsigned* db = &Bs[row][c4 * 4];
            db[0] = f2tf(vb.x); db[1] = f2tf(vb.y); db[2] = f2tf(vb.z); db[3] = f2tf(vb.w);
        }
        __syncthreads();

#pragma unroll
        for (int ks = 0; ks < 4; ks++) {
            const int k0 = ks * 8;
            unsigned af[2][4];
#pragma unroll
            for (int mt = 0; mt < 2; mt++) {
                int r0 = wm + mt * 16;
                af[mt][0] = As[r0 + lq][k0 + kq];
                af[mt][1] = As[r0 + 8 + lq][k0 + kq];
                af[mt][2] = As[r0 + lq][k0 + 4 + kq];
                af[mt][3] = As[r0 + 8 + lq][k0 + 4 + kq];
            }
#pragma unroll
            for (int nt = 0; nt < 8; nt++) {
                unsigned b0 = Bs[wn + nt * 8 + lq][k0 + kq];
                unsigned b1 = Bs[wn + nt * 8 + lq][k0 + 4 + kq];
                mma8(acc[0][nt], af[0], b0, b1);
                mma8(acc[1][nt], af[1], b0, b1);
            }
        }
        __syncthreads();
    }

    // epilogue
#pragma unroll
    for (int mt = 0; mt < 2; mt++) {
        int rA = bm + wm + mt * 16 + lq;
#pragma unroll
        for (int nt = 0; nt < 8; nt++) {
            int c0 = bn + wn + nt * 8 + 2 * kq;
            float b0 = bias[c0], b1 = bias[c0 + 1];
            float2 vA = make_float2((acc[mt][nt][0] + b0) * outScale,
                                    (acc[mt][nt][1] + b1) * outScale);
            float2 vB = make_float2((acc[mt][nt][2] + b0) * outScale,
                                    (acc[mt][nt][3] + b1) * outScale);
            storeC<PERM>(C, rA, c0, vA, S);
            storeC<PERM>(C, rA + 8, c0, vB, S);
        }
    }
}

// ---------------- Flash attention ----------------
// grid: (SQ/64, H, B); 128 threads; per-CTA: 64 q-rows, stream 64-key tiles.
#define ATT_STRIDE 68
#define ATT_TILE_U (64 * ATT_STRIDE)
#define ATT_SMEM_UINTS (4 * ATT_TILE_U + 64)

__global__ void __launch_bounds__(128) attn_kernel(const int* __restrict__ kvmask)
{
    extern __shared__ unsigned smu[];
    unsigned* Qs = smu;
    unsigned* Ks = smu + ATT_TILE_U;
    unsigned* Vs = smu + 2 * ATT_TILE_U;
    unsigned* Ps = smu + 3 * ATT_TILE_U;
    float* maskS = (float*)(smu + 4 * ATT_TILE_U);

    const int tid  = threadIdx.x;
    const int lane = tid & 31;
    const int warp = tid >> 5;
    const int lq   = lane >> 2;
    const int kq   = lane & 3;
    const int qt = blockIdx.x, h = blockIdx.y, b = blockIdx.z;

    const float* Qg = g_Qp + (((size_t)b * NHEAD + h) * SEQ_Q + qt * 64) * HDIM;
    const float* Kg = g_Kp + ((size_t)b * NHEAD + h) * SEQ_KV * HDIM;
    const float* Vg = g_Vp + ((size_t)b * NHEAD + h) * SEQ_KV * HDIM;
    const int*   mg = kvmask + (size_t)b * SEQ_KV;

    // Q tile -> smem (already pre-scaled by 1/sqrt(D) in projection)
#pragma unroll
    for (int p = 0; p < 8; p++) {
        int i4  = p * 128 + tid;
        int row = i4 >> 4;
        int c4  = i4 & 15;
        float4 v = *(const float4*)(Qg + row * HDIM + c4 * 4);
        unsigned* d = Qs + row * ATT_STRIDE + c4 * 4;
        d[0] = f2tf(v.x); d[1] = f2tf(v.y); d[2] = f2tf(v.z); d[3] = f2tf(v.w);
    }
    __syncthreads();

    const int row0 = warp * 16;
    unsigned qf[8][4];
#pragma unroll
    for (int ks = 0; ks < 8; ks++) {
        qf[ks][0] = Qs[(row0 + lq) * ATT_STRIDE + ks * 8 + kq];
        qf[ks][1] = Qs[(row0 + 8 + lq) * ATT_STRIDE + ks * 8 + kq];
        qf[ks][2] = Qs[(row0 + lq) * ATT_STRIDE + ks * 8 + 4 + kq];
        qf[ks][3] = Qs[(row0 + 8 + lq) * ATT_STRIDE + ks * 8 + 4 + kq];
    }

    float o[8][4];
#pragma unroll
    for (int nt = 0; nt < 8; nt++)
#pragma unroll
        for (int r = 0; r < 4; r++) o[nt][r] = 0.0f;

    float mAv = -1e30f, mBv = -1e30f, lAv = 0.0f, lBv = 0.0f;

    for (int kt = 0; kt < SEQ_KV / 64; kt++) {
        __syncthreads();  // previous iteration's reads of Ks/Vs complete
#pragma unroll
        for (int p = 0; p < 8; p++) {
            int i4  = p * 128 + tid;
            int row = i4 >> 4;
            int c4  = i4 & 15;
            float4 vk = *(const float4*)(Kg + (size_t)(kt * 64 + row) * HDIM + c4 * 4);
            unsigned* dk = Ks + row * ATT_STRIDE + c4 * 4;
            dk[0] = f2tf(vk.x); dk[1] = f2tf(vk.y); dk[2] = f2tf(vk.z); dk[3] = f2tf(vk.w);
            float4 vv = *(const float4*)(Vg + (size_t)(kt * 64 + row) * HDIM + c4 * 4);
            unsigned* dv = Vs + row * ATT_STRIDE + c4 * 4;
            dv[0] = f2tf(vv.x); dv[1] = f2tf(vv.y); dv[2] = f2tf(vv.z); dv[3] = f2tf(vv.w);
        }
        if (tid < 64) maskS[tid] = mg[kt * 64 + tid] ? 0.0f : -3.0e38f;
        __syncthreads();

        // S = Q * K^T  (rows row0..row0+15 per warp, all 64 keys)
        float sacc[8][4];
#pragma unroll
        for (int nt = 0; nt < 8; nt++)
#pragma unroll
            for (int r = 0; r < 4; r++) sacc[nt][r] = 0.0f;

#pragma unroll
        for (int ks = 0; ks < 8; ks++) {
#pragma unroll
            for (int nt = 0; nt < 8; nt++) {
                unsigned b0 = Ks[(nt * 8 + lq) * ATT_STRIDE + ks * 8 + kq];
                unsigned b1 = Ks[(nt * 8 + lq) * ATT_STRIDE + ks * 8 + 4 + kq];
                mma8(sacc[nt], qf[ks], b0, b1);
            }
        }

        // mask + row max
        float tmA = -3.0e38f, tmB = -3.0e38f;
#pragma unroll
        for (int nt = 0; nt < 8; nt++) {
            float m0 = maskS[nt * 8 + 2 * kq];
            float m1 = maskS[nt * 8 + 2 * kq + 1];
            sacc[nt][0] += m0; sacc[nt][1] += m1;
            sacc[nt][2] += m0; sacc[nt][3] += m1;
            tmA = fmaxf(tmA, fmaxf(sacc[nt][0], sacc[nt][1]));
            tmB = fmaxf(tmB, fmaxf(sacc[nt][2], sacc[nt][3]));
        }
        tmA = fmaxf(tmA, __shfl_xor_sync(0xffffffffu, tmA, 1));
        tmA = fmaxf(tmA, __shfl_xor_sync(0xffffffffu, tmA, 2));
        tmB = fmaxf(tmB, __shfl_xor_sync(0xffffffffu, tmB, 1));
        tmB = fmaxf(tmB, __shfl_xor_sync(0xffffffffu, tmB, 2));

        float mnA = fmaxf(mAv, tmA), mnB = fmaxf(mBv, tmB);
        float aA = __expf(mAv - mnA), aB = __expf(mBv - mnB);
        mAv = mnA; mBv = mnB;

        float sA = 0.0f, sB = 0.0f;
#pragma unroll
        for (int nt = 0; nt < 8; nt++) {
            float p0 = __expf(sacc[nt][0] - mnA);
            float p1 = __expf(sacc[nt][1] - mnA);
            float p2 = __expf(sacc[nt][2] - mnB);
            float p3 = __expf(sacc[nt][3] - mnB);
            sA += p0 + p1;
            sB += p2 + p3;
            Ps[(row0 + lq) * ATT_STRIDE + nt * 8 + 2 * kq]         = f2tf(p0);
            Ps[(row0 + lq) * ATT_STRIDE + nt * 8 + 2 * kq + 1]     = f2tf(p1);
            Ps[(row0 + 8 + lq) * ATT_STRIDE + nt * 8 + 2 * kq]     = f2tf(p2);
            Ps[(row0 + 8 + lq) * ATT_STRIDE + nt * 8 + 2 * kq + 1] = f2tf(p3);
            o[nt][0] *= aA; o[nt][1] *= aA;
            o[nt][2] *= aB; o[nt][3] *= aB;
        }
        sA += __shfl_xor_sync(0xffffffffu, sA, 1);
        sA += __shfl_xor_sync(0xffffffffu, sA, 2);
        sB += __shfl_xor_sync(0xffffffffu, sB, 1);
        sB += __shfl_xor_sync(0xffffffffu, sB, 2);
        lAv = lAv * aA + sA;
        lBv = lBv * aB + sB;

        __syncwarp();  // P smem visible within warp

        // O += P * V
#pragma unroll
        for (int ks = 0; ks < 8; ks++) {
            unsigned pf[4];
            pf[0] = Ps[(row0 + lq) * ATT_STRIDE + ks * 8 + kq];
            pf[1] = Ps[(row0 + 8 + lq) * ATT_STRIDE + ks * 8 + kq];
            pf[2] = Ps[(row0 + lq) * ATT_STRIDE + ks * 8 + 4 + kq];
            pf[3] = Ps[(row0 + 8 + lq) * ATT_STRIDE + ks * 8 + 4 + kq];
#pragma unroll
            for (int nt = 0; nt < 8; nt++) {
                unsigned b0 = Vs[(ks * 8 + kq) * ATT_STRIDE + nt * 8 + lq];
                unsigned b1 = Vs[(ks * 8 + 4 + kq) * ATT_STRIDE + nt * 8 + lq];
                mma8(o[nt], pf, b0, b1);
            }
        }
    }

    // normalize + write out to [B*SQ, E]
    float rA = 1.0f / lAv, rB = 1.0f / lBv;
    int qA = qt * 64 + row0 + lq;
    float* outBase = g_attn + (size_t)b * SEQ_Q * E_DIM;
#pragma unroll
    for (int nt = 0; nt < 8; nt++) {
        int c = h * HDIM + nt * 8 + 2 * kq;
        *(float2*)(outBase + (size_t)qA * E_DIM + c) =
            make_float2(o[nt][0] * rA, o[nt][1] * rA);
        *(float2*)(outBase + (size_t)(qA + 8) * E_DIM + c) =
            make_float2(o[nt][2] * rB, o[nt][3] * rB);
    }
}

// ---------------- residual + LayerNorm ----------------
__global__ void __launch_bounds__(256) ln_kernel(
    const float* __restrict__ query, const float* __restrict__ proj,
    const float* __restrict__ gamma, const float* __restrict__ beta,
    float* __restrict__ out)
{
    __shared__ float rs[8], rs2[8];
    const int row = blockIdx.x, tid = threadIdx.x;
    const int lane = tid & 31, warp = tid >> 5;
    const size_t base = (size_t)row * E_DIM + tid * 4;

    float4 q = *(const float4*)(query + base);
    float4 p = *(const float4*)(proj + base);
    float x0 = q.x + p.x, x1 = q.y + p.y, x2 = q.z + p.z, x3 = q.w + p.w;
    float s  = x0 + x1 + x2 + x3;
    float s2 = x0 * x0 + x1 * x1 + x2 * x2 + x3 * x3;
#pragma unroll
    for (int off = 16; off; off >>= 1) {
        s  += __shfl_xor_sync(0xffffffffu, s, off);
        s2 += __shfl_xor_sync(0xffffffffu, s2, off);
    }
    if (lane == 0) { rs[warp] = s; rs2[warp] = s2; }
    __syncthreads();
    s = 0.0f; s2 = 0.0f;
#pragma unroll
    for (int i = 0; i < 8; i++) { s += rs[i]; s2 += rs2[i]; }

    float mean = s * (1.0f / E_DIM);
    float var  = s2 * (1.0f / E_DIM) - mean * mean;
    float rstd = rsqrtf(var + LN_EPS);

    float4 g  = *(const float4*)(gamma + tid * 4);
    float4 bb = *(const float4*)(beta + tid * 4);
    float4 r;
    r.x = (x0 - mean) * rstd * g.x + bb.x;
    r.y = (x1 - mean) * rstd * g.y + bb.y;
    r.z = (x2 - mean) * rstd * g.z + bb.z;
    r.w = (x3 - mean) * rstd * g.w + bb.w;
    *(float4*)(out + base) = r;
}

// ---------------- launch ----------------
extern "C" void kernel_launch(void* const* d_in, const int* in_sizes, int n_in,
                              void* d_out, int out_size)
{
    const float* query     = (const float*)d_in[0];
    const float* key_value = (const float*)d_in[1];
    const int*   kvmask    = (const int*)d_in[2];
    const float* Wq = (const float*)d_in[3];
    const float* bq = (const float*)d_in[4];
    const float* Wk = (const float*)d_in[5];
    const float* bk = (const float*)d_in[6];
    const float* Wv = (const float*)d_in[7];
    const float* bv = (const float*)d_in[8];
    const float* Wo = (const float*)d_in[9];
    const float* bo = (const float*)d_in[10];
    const float* gamma = (const float*)d_in[11];
    const float* beta  = (const float*)d_in[12];
    float* out = (float*)d_out;

    float *Qp, *Kp, *Vp, *attn, *proj;
    cudaGetSymbolAddress((void**)&Qp, g_Qp);
    cudaGetSymbolAddress((void**)&Kp, g_Kp);
    cudaGetSymbolAddress((void**)&Vp, g_Vp);
    cudaGetSymbolAddress((void**)&attn, g_attn);
    cudaGetSymbolAddress((void**)&proj, g_proj);

    const int smemAttn = ATT_SMEM_UINTS * 4;
    cudaFuncSetAttribute(attn_kernel, cudaFuncAttributeMaxDynamicSharedMemorySize, smemAttn);

    // Q projection (scale 1/sqrt(D) folded in), K and V projections
    gemm_tf32_kernel<true><<<dim3(BATCH * SEQ_Q / 128, E_DIM / 128), 256>>>(
        query, Wq, bq, Qp, BATCH * SEQ_Q, SEQ_Q, 0.125f);
    gemm_tf32_kernel<true><<<dim3(BATCH * SEQ_KV / 128, E_DIM / 128), 256>>>(
        key_value, Wk, bk, Kp, BATCH * SEQ_KV, SEQ_KV, 1.0f);
    gemm_tf32_kernel<true><<<dim3(BATCH * SEQ_KV / 128, E_DIM / 128), 256>>>(
        key_value, Wv, bv, Vp, BATCH * SEQ_KV, SEQ_KV, 1.0f);

    attn_kernel<<<dim3(SEQ_Q / 64, NHEAD, BATCH), 128, smemAttn>>>(kvmask);

    gemm_tf32_kernel<false><<<dim3(BATCH * SEQ_Q / 128, E_DIM / 128), 256>>>(
        attn, Wo, bo, proj, BATCH * SEQ_Q, SEQ_Q, 1.0f);

    ln_kernel<<<BATCH * SEQ_Q, 256>>>(query, proj, gamma, beta, out);
}

// round 3
// speedup vs baseline: 1.3884x; 1.3884x over previous
#include <cuda_runtime.h>
#include <cstdint>
#include <cstddef>

#define E_DIM  1024
#define NHEAD  16
#define HDIM   64
#define BATCH  2
#define SEQ_Q  1024
#define SEQ_KV 4096
#define LN_EPS 1e-5f

// ---------------- scratch (no allocations allowed) ----------------
__device__ float g_Qp[(size_t)BATCH * NHEAD * SEQ_Q * HDIM];     // [B,H,SQ,D]  (tf32-rounded)
__device__ float g_Kp[(size_t)BATCH * NHEAD * SEQ_KV * HDIM];    // [B,H,SKV,D] (tf32-rounded)
__device__ float g_Vp[(size_t)BATCH * NHEAD * SEQ_KV * HDIM];    // [B,H,SKV,D] (tf32-rounded)
__device__ float g_attn[(size_t)BATCH * SEQ_Q * E_DIM];          // [B*SQ, E]   (tf32-rounded)
__device__ float g_proj[(size_t)BATCH * SEQ_Q * E_DIM];          // [B*SQ, E]
__device__ float g_qr [(size_t)BATCH * SEQ_Q * E_DIM];           // rounded query
__device__ float g_kvr[(size_t)BATCH * SEQ_KV * E_DIM];          // rounded key_value
__device__ float g_w  [(size_t)4 * E_DIM * E_DIM];               // rounded Wq,Wk,Wv,Wo

// ---------------- helpers ----------------
__device__ __forceinline__ float f2tff(float f) {
    unsigned u;
    asm("cvt.rna.tf32.f32 %0, %1;" : "=r"(u) : "f"(f));
    return __uint_as_float(u);
}

__device__ __forceinline__ void mma8(float* c, const unsigned* a, unsigned b0, unsigned b1) {
    asm volatile(
        "mma.sync.aligned.m16n8k8.row.col.f32.tf32.tf32.f32 "
        "{%0,%1,%2,%3}, {%4,%5,%6,%7}, {%8,%9}, {%0,%1,%2,%3};\n"
        : "+f"(c[0]), "+f"(c[1]), "+f"(c[2]), "+f"(c[3])
        : "r"(a[0]), "r"(a[1]), "r"(a[2]), "r"(a[3]), "r"(b0), "r"(b1));
}

__device__ __forceinline__ void cpasync16(const float* dst, const float* src) {
    uint32_t d = (uint32_t)__cvta_generic_to_shared(dst);
    asm volatile("cp.async.cg.shared.global [%0], [%1], 16;" :: "r"(d), "l"(src));
}
#define CP_COMMIT() asm volatile("cp.async.commit_group;" ::: "memory")
#define CP_WAIT(n)  asm volatile("cp.async.wait_group %0;" :: "n"(n) : "memory")

// ---------------- pre-round kernels (fp32 -> tf32-rounded fp32) ----------------
__global__ void __launch_bounds__(256) round_one(const float* __restrict__ in,
                                                 float* __restrict__ out, int n4) {
    int i = blockIdx.x * 256 + threadIdx.x;
    if (i < n4) {
        float4 v = ((const float4*)in)[i];
        float4 r;
        r.x = f2tff(v.x); r.y = f2tff(v.y); r.z = f2tff(v.z); r.w = f2tff(v.w);
        ((float4*)out)[i] = r;
    }
}

__global__ void __launch_bounds__(256) round_w(const float* __restrict__ a,
                                               const float* __restrict__ b,
                                               const float* __restrict__ c,
                                               const float* __restrict__ d,
                                               float* __restrict__ o) {
    const float* in = (blockIdx.y == 0) ? a : (blockIdx.y == 1) ? b : (blockIdx.y == 2) ? c : d;
    float* out = o + (size_t)blockIdx.y * E_DIM * E_DIM;
    int i = blockIdx.x * 256 + threadIdx.x;   // exactly 1024*256 = 262144 float4
    float4 v = ((const float4*)in)[i];
    float4 r;
    r.x = f2tff(v.x); r.y = f2tff(v.y); r.z = f2tff(v.z); r.w = f2tff(v.w);
    ((float4*)out)[i] = r;
}

// ---------------- GEMM: C[M,N] = A[M,K] * W[N,K]^T + bias (inputs tf32-rounded) ----------------
template <bool PERM>
__device__ __forceinline__ void storeC(float* __restrict__ C, int r, int c, float2 v, int S) {
    if (PERM) {
        int b = r / S;
        int s = r - b * S;
        int h = c >> 6;
        int d = c & 63;
        *(float2*)(C + (((size_t)b * NHEAD + h) * S + s) * HDIM + d) = v;
    } else {
        *(float2*)(C + (size_t)r * E_DIM + c) = v;
    }
}

#define G_STG 4608   // 128*36 floats per stage
#define GEMM_SMEM_BYTES (4 * G_STG * 4)

template <bool PERM>
__global__ void __launch_bounds__(256) gemm_tf32_kernel(
    const float* __restrict__ A, const float* __restrict__ W,
    const float* __restrict__ bias, float* __restrict__ C,
    int S, float outScale)
{
    extern __shared__ float sm[];
    float* As = sm;                // [2][128][36]
    float* Bs = sm + 2 * G_STG;    // [2][128][36]

    const int tid  = threadIdx.x;
    const int lane = tid & 31;
    const int warp = tid >> 5;
    const int lq   = lane >> 2;
    const int kq   = lane & 3;
    const int bm   = blockIdx.x * 128;
    const int bn   = blockIdx.y * 128;
    const int wm   = (warp & 3) * 32;
    const int wn   = (warp >> 2) * 64;

    auto issue = [&](int kt, int s) {
#pragma unroll
        for (int p = 0; p < 4; p++) {
            int i4  = p * 256 + tid;
            int row = i4 >> 3;
            int c4  = i4 & 7;
            cpasync16(As + s * G_STG + row * 36 + c4 * 4,
                      A + (size_t)(bm + row) * E_DIM + kt * 32 + c4 * 4);
            cpasync16(Bs + s * G_STG + row * 36 + c4 * 4,
                      W + (size_t)(bn + row) * E_DIM + kt * 32 + c4 * 4);
        }
        CP_COMMIT();
    };

    float acc[2][8][4];
#pragma unroll
    for (int mt = 0; mt < 2; mt++)
#pragma unroll
        for (int nt = 0; nt < 8; nt++)
#pragma unroll
            for (int r = 0; r < 4; r++) acc[mt][nt][r] = 0.0f;

    issue(0, 0);
    issue(1, 1);

#pragma unroll 1
    for (int kt = 0; kt < 32; kt++) {
        if (kt + 1 < 32) { CP_WAIT(1); } else { CP_WAIT(0); }
        __syncthreads();
        const float* Ast = As + (kt & 1) * G_STG;
        const float* Bst = Bs + (kt & 1) * G_STG;

#pragma unroll
        for (int ks = 0; ks < 4; ks++) {
            const int k0 = ks * 8;
            unsigned af[2][4];
#pragma unroll
            for (int mt = 0; mt < 2; mt++) {
                int r0 = wm + mt * 16;
                af[mt][0] = __float_as_uint(Ast[(r0 + lq) * 36 + k0 + kq]);
                af[mt][1] = __float_as_uint(Ast[(r0 + 8 + lq) * 36 + k0 + kq]);
                af[mt][2] = __float_as_uint(Ast[(r0 + lq) * 36 + k0 + 4 + kq]);
                af[mt][3] = __float_as_uint(Ast[(r0 + 8 + lq) * 36 + k0 + 4 + kq]);
            }
#pragma unroll
            for (int nt = 0; nt < 8; nt++) {
                unsigned b0 = __float_as_uint(Bst[(wn + nt * 8 + lq) * 36 + k0 + kq]);
                unsigned b1 = __float_as_uint(Bst[(wn + nt * 8 + lq) * 36 + k0 + 4 + kq]);
                mma8(acc[0][nt], af[0], b0, b1);
                mma8(acc[1][nt], af[1], b0, b1);
            }
        }
        __syncthreads();
        if (kt + 2 < 32) issue(kt + 2, kt & 1);
    }

    // epilogue
#pragma unroll
    for (int mt = 0; mt < 2; mt++) {
        int rA = bm + wm + mt * 16 + lq;
#pragma unroll
        for (int nt = 0; nt < 8; nt++) {
            int c0 = bn + wn + nt * 8 + 2 * kq;
            float b0 = bias[c0], b1 = bias[c0 + 1];
            float v0 = (acc[mt][nt][0] + b0) * outScale;
            float v1 = (acc[mt][nt][1] + b1) * outScale;
            float v2 = (acc[mt][nt][2] + b0) * outScale;
            float v3 = (acc[mt][nt][3] + b1) * outScale;
            if (PERM) { v0 = f2tff(v0); v1 = f2tff(v1); v2 = f2tff(v2); v3 = f2tff(v3); }
            storeC<PERM>(C, rA, c0, make_float2(v0, v1), S);
            storeC<PERM>(C, rA + 8, c0, make_float2(v2, v3), S);
        }
    }
}

// ---------------- Flash attention v2 ----------------
// grid (SQ/128, H, B), 128 threads; warp = 32 q-rows (2 row-blocks of 16).
// cp.async double-buffered K/V, shuffle-based P fragments (no P smem).
#define QSTR 68
#define KSTR 68
#define VSTR 72
#define KTILE_F (64 * KSTR)
#define VTILE_F (64 * VSTR)
#define QOFF 0
#define KOFF (128 * QSTR)
#define VOFF (KOFF + 2 * KTILE_F)
#define MOFF (VOFF + 2 * VTILE_F)
#define ATT_SMEM_BYTES ((MOFF + 128) * 4)

__global__ void __launch_bounds__(128) attn_kernel(const int* __restrict__ kvmask)
{
    extern __shared__ float sm[];

    const int tid  = threadIdx.x;
    const int lane = tid & 31;
    const int warp = tid >> 5;
    const int lq   = lane >> 2;
    const int kq   = lane & 3;
    const int qt = blockIdx.x, h = blockIdx.y, b = blockIdx.z;

    const float* Qg = g_Qp + (((size_t)b * NHEAD + h) * SEQ_Q + qt * 128) * HDIM;
    const float* Kg = g_Kp + ((size_t)b * NHEAD + h) * SEQ_KV * HDIM;
    const float* Vg = g_Vp + ((size_t)b * NHEAD + h) * SEQ_KV * HDIM;
    const int*   mg = kvmask + (size_t)b * SEQ_KV;

    // Q tile -> smem (one-time)
#pragma unroll
    for (int p = 0; p < 16; p++) {
        int i4  = p * 128 + tid;
        int row = i4 >> 4;
        int c4  = i4 & 15;
        cpasync16(sm + QOFF + row * QSTR + c4 * 4, Qg + row * HDIM + c4 * 4);
    }
    CP_COMMIT();
    CP_WAIT(0);
    __syncthreads();

    const int r0 = warp * 32;
    unsigned qf[2][8][4];
#pragma unroll
    for (int rb = 0; rb < 2; rb++)
#pragma unroll
        for (int ks = 0; ks < 8; ks++) {
            int rr = r0 + rb * 16;
            qf[rb][ks][0] = __float_as_uint(sm[QOFF + (rr + lq) * QSTR + ks * 8 + kq]);
            qf[rb][ks][1] = __float_as_uint(sm[QOFF + (rr + 8 + lq) * QSTR + ks * 8 + kq]);
            qf[rb][ks][2] = __float_as_uint(sm[QOFF + (rr + lq) * QSTR + ks * 8 + 4 + kq]);
            qf[rb][ks][3] = __float_as_uint(sm[QOFF + (rr + 8 + lq) * QSTR + ks * 8 + 4 + kq]);
        }
    __syncthreads();

    auto issue = [&](int kt, int s) {
        const float* kp = Kg + (size_t)kt * 64 * HDIM;
        const float* vp = Vg + (size_t)kt * 64 * HDIM;
#pragma unroll
        for (int p = 0; p < 8; p++) {
            int i4  = p * 128 + tid;
            int row = i4 >> 4;
            int c4  = i4 & 15;
            cpasync16(sm + KOFF + s * KTILE_F + row * KSTR + c4 * 4, kp + row * HDIM + c4 * 4);
            cpasync16(sm + VOFF + s * VTILE_F + row * VSTR + c4 * 4, vp + row * HDIM + c4 * 4);
        }
        if (tid < 64) sm[MOFF + s * 64 + tid] = mg[kt * 64 + tid] ? 0.0f : -3.0e38f;
        CP_COMMIT();
    };

    float o[2][8][4];
#pragma unroll
    for (int rb = 0; rb < 2; rb++)
#pragma unroll
        for (int nt = 0; nt < 8; nt++)
#pragma unroll
            for (int r = 0; r < 4; r++) o[rb][nt][r] = 0.0f;

    float mA[2] = {-1e30f, -1e30f}, mB[2] = {-1e30f, -1e30f};
    float lA[2] = {0.0f, 0.0f},     lB[2] = {0.0f, 0.0f};

    issue(0, 0);
    issue(1, 1);

    const int  srcA = (lane & ~3) | (kq >> 1);
    const int  srcB = srcA + 2;
    const bool par  = (kq & 1);

#pragma unroll 1
    for (int kt = 0; kt < SEQ_KV / 64; kt++) {
        if (kt + 1 < SEQ_KV / 64) { CP_WAIT(1); } else { CP_WAIT(0); }
        __syncthreads();
        const int s = kt & 1;
        const float* Kst = sm + KOFF + s * KTILE_F;
        const float* Vst = sm + VOFF + s * VTILE_F;
        const float* msk = sm + MOFF + s * 64;

        // S = Q K^T
        float sacc[2][8][4];
#pragma unroll
        for (int rb = 0; rb < 2; rb++)
#pragma unroll
            for (int nt = 0; nt < 8; nt++)
#pragma unroll
                for (int r = 0; r < 4; r++) sacc[rb][nt][r] = 0.0f;

#pragma unroll
        for (int ks = 0; ks < 8; ks++) {
#pragma unroll
            for (int nt = 0; nt < 8; nt++) {
                unsigned b0 = __float_as_uint(Kst[(nt * 8 + lq) * KSTR + ks * 8 + kq]);
                unsigned b1 = __float_as_uint(Kst[(nt * 8 + lq) * KSTR + ks * 8 + 4 + kq]);
                mma8(sacc[0][nt], qf[0][ks], b0, b1);
                mma8(sacc[1][nt], qf[1][ks], b0, b1);
            }
        }

        // mask + row max
        float tm[2][2] = {{-3.0e38f, -3.0e38f}, {-3.0e38f, -3.0e38f}};
#pragma unroll
        for (int nt = 0; nt < 8; nt++) {
            float m0 = msk[nt * 8 + 2 * kq];
            float m1 = msk[nt * 8 + 2 * kq + 1];
#pragma unroll
            for (int rb = 0; rb < 2; rb++) {
                sacc[rb][nt][0] += m0; sacc[rb][nt][1] += m1;
                sacc[rb][nt][2] += m0; sacc[rb][nt][3] += m1;
                tm[rb][0] = fmaxf(tm[rb][0], fmaxf(sacc[rb][nt][0], sacc[rb][nt][1]));
                tm[rb][1] = fmaxf(tm[rb][1], fmaxf(sacc[rb][nt][2], sacc[rb][nt][3]));
            }
        }
#pragma unroll
        for (int rb = 0; rb < 2; rb++)
#pragma unroll
            for (int j = 0; j < 2; j++) {
                tm[rb][j] = fmaxf(tm[rb][j], __shfl_xor_sync(0xffffffffu, tm[rb][j], 1));
                tm[rb][j] = fmaxf(tm[rb][j], __shfl_xor_sync(0xffffffffu, tm[rb][j], 2));
            }

        float aA[2], aB[2];
#pragma unroll
        for (int rb = 0; rb < 2; rb++) {
            float mnA = fmaxf(mA[rb], tm[rb][0]);
            float mnB = fmaxf(mB[rb], tm[rb][1]);
            aA[rb] = __expf(mA[rb] - mnA);
            aB[rb] = __expf(mB[rb] - mnB);
            mA[rb] = mnA; mB[rb] = mnB;
        }

        float sums[2][2] = {{0.0f, 0.0f}, {0.0f, 0.0f}};
#pragma unroll
        for (int nt = 0; nt < 8; nt++) {
#pragma unroll
            for (int rb = 0; rb < 2; rb++) {
                float p0 = f2tff(__expf(sacc[rb][nt][0] - mA[rb]));
                float p1 = f2tff(__expf(sacc[rb][nt][1] - mA[rb]));
                float p2 = f2tff(__expf(sacc[rb][nt][2] - mB[rb]));
                float p3 = f2tff(__expf(sacc[rb][nt][3] - mB[rb]));
                sums[rb][0] += p0 + p1;
                sums[rb][1] += p2 + p3;
                sacc[rb][nt][0] = p0; sacc[rb][nt][1] = p1;
                sacc[rb][nt][2] = p2; sacc[rb][nt][3] = p3;
                o[rb][nt][0] *= aA[rb]; o[rb][nt][1] *= aA[rb];
                o[rb][nt][2] *= aB[rb]; o[rb][nt][3] *= aB[rb];
            }
        }
#pragma unroll
        for (int rb = 0; rb < 2; rb++) {
#pragma unroll
            for (int j = 0; j < 2; j++) {
                sums[rb][j] += __shfl_xor_sync(0xffffffffu, sums[rb][j], 1);
                sums[rb][j] += __shfl_xor_sync(0xffffffffu, sums[rb][j], 2);
            }
            lA[rb] = lA[rb] * aA[rb] + sums[rb][0];
            lB[rb] = lB[rb] * aB[rb] + sums[rb][1];
        }

        // O += P V  (P fragments via shuffle from C-layout)
#pragma unroll
        for (int ks = 0; ks < 8; ks++) {
            unsigned pf[2][4];
#pragma unroll
            for (int rb = 0; rb < 2; rb++) {
                float u0 = __shfl_sync(0xffffffffu, sacc[rb][ks][0], srcA);
                float u1 = __shfl_sync(0xffffffffu, sacc[rb][ks][1], srcA);
                float u2 = __shfl_sync(0xffffffffu, sacc[rb][ks][2], srcA);
                float u3 = __shfl_sync(0xffffffffu, sacc[rb][ks][3], srcA);
                float w0 = __shfl_sync(0xffffffffu, sacc[rb][ks][0], srcB);
                float w1 = __shfl_sync(0xffffffffu, sacc[rb][ks][1], srcB);
                float w2 = __shfl_sync(0xffffffffu, sacc[rb][ks][2], srcB);
                float w3 = __shfl_sync(0xffffffffu, sacc[rb][ks][3], srcB);
                pf[rb][0] = __float_as_uint(par ? u1 : u0);
                pf[rb][1] = __float_as_uint(par ? u3 : u2);
                pf[rb][2] = __float_as_uint(par ? w1 : w0);
                pf[rb][3] = __float_as_uint(par ? w3 : w2);
            }
#pragma unroll
            for (int nt = 0; nt < 8; nt++) {
                unsigned b0 = __float_as_uint(Vst[(ks * 8 + kq) * VSTR + nt * 8 + lq]);
                unsigned b1 = __float_as_uint(Vst[(ks * 8 + 4 + kq) * VSTR + nt * 8 + lq]);
                mma8(o[0][nt], pf[0], b0, b1);
                mma8(o[1][nt], pf[1], b0, b1);
            }
        }
        __syncthreads();
        if (kt + 2 < SEQ_KV / 64) issue(kt + 2, s);
    }

    // normalize + round + write [B*SQ, E]
    float* outBase = g_attn + (size_t)b * SEQ_Q * E_DIM;
#pragma unroll
    for (int rb = 0; rb < 2; rb++) {
        float rA = 1.0f / lA[rb], rB = 1.0f / lB[rb];
        int qA = qt * 128 + r0 + rb * 16 + lq;
#pragma unroll
        for (int nt = 0; nt < 8; nt++) {
            int c = h * HDIM + nt * 8 + 2 * kq;
            *(float2*)(outBase + (size_t)qA * E_DIM + c) =
                make_float2(f2tff(o[rb][nt][0] * rA), f2tff(o[rb][nt][1] * rA));
            *(float2*)(outBase + (size_t)(qA + 8) * E_DIM + c) =
                make_float2(f2tff(o[rb][nt][2] * rB), f2tff(o[rb][nt][3] * rB));
        }
    }
}

// ---------------- residual + LayerNorm ----------------
__global__ void __launch_bounds__(256) ln_kernel(
    const float* __restrict__ query, const float* __restrict__ proj,
    const float* __restrict__ gamma, const float* __restrict__ beta,
    float* __restrict__ out)
{
    __shared__ float rs[8], rs2[8];
    const int row = blockIdx.x, tid = threadIdx.x;
    const int lane = tid & 31, warp = tid >> 5;
    const size_t base = (size_t)row * E_DIM + tid * 4;

    float4 q = *(const float4*)(query + base);
    float4 p = *(const float4*)(proj + base);
    float x0 = q.x + p.x, x1 = q.y + p.y, x2 = q.z + p.z, x3 = q.w + p.w;
    float s  = x0 + x1 + x2 + x3;
    float s2 = x0 * x0 + x1 * x1 + x2 * x2 + x3 * x3;
#pragma unroll
    for (int off = 16; off; off >>= 1) {
        s  += __shfl_xor_sync(0xffffffffu, s, off);
        s2 += __shfl_xor_sync(0xffffffffu, s2, off);
    }
    if (lane == 0) { rs[warp] = s; rs2[warp] = s2; }
    __syncthreads();
    s = 0.0f; s2 = 0.0f;
#pragma unroll
    for (int i = 0; i < 8; i++) { s += rs[i]; s2 += rs2[i]; }

    float mean = s * (1.0f / E_DIM);
    float var  = s2 * (1.0f / E_DIM) - mean * mean;
    float rstd = rsqrtf(var + LN_EPS);

    float4 g  = *(const float4*)(gamma + tid * 4);
    float4 bb = *(const float4*)(beta + tid * 4);
    float4 r;
    r.x = (x0 - mean) * rstd * g.x + bb.x;
    r.y = (x1 - mean) * rstd * g.y + bb.y;
    r.z = (x2 - mean) * rstd * g.z + bb.z;
    r.w = (x3 - mean) * rstd * g.w + bb.w;
    *(float4*)(out + base) = r;
}

// ---------------- launch ----------------
extern "C" void kernel_launch(void* const* d_in, const int* in_sizes, int n_in,
                              void* d_out, int out_size)
{
    const float* query     = (const float*)d_in[0];
    const float* key_value = (const float*)d_in[1];
    const int*   kvmask    = (const int*)d_in[2];
    const float* Wq = (const float*)d_in[3];
    const float* bq = (const float*)d_in[4];
    const float* Wk = (const float*)d_in[5];
    const float* bk = (const float*)d_in[6];
    const float* Wv = (const float*)d_in[7];
    const float* bv = (const float*)d_in[8];
    const float* Wo = (const float*)d_in[9];
    const float* bo = (const float*)d_in[10];
    const float* gamma = (const float*)d_in[11];
    const float* beta  = (const float*)d_in[12];
    float* out = (float*)d_out;

    float *Qp, *Kp, *Vp, *attn, *proj, *qr, *kvr, *w;
    cudaGetSymbolAddress((void**)&Qp, g_Qp);
    cudaGetSymbolAddress((void**)&Kp, g_Kp);
    cudaGetSymbolAddress((void**)&Vp, g_Vp);
    cudaGetSymbolAddress((void**)&attn, g_attn);
    cudaGetSymbolAddress((void**)&proj, g_proj);
    cudaGetSymbolAddress((void**)&qr, g_qr);
    cudaGetSymbolAddress((void**)&kvr, g_kvr);
    cudaGetSymbolAddress((void**)&w, g_w);

    cudaFuncSetAttribute(gemm_tf32_kernel<true>,
                         cudaFuncAttributeMaxDynamicSharedMemorySize, GEMM_SMEM_BYTES);
    cudaFuncSetAttribute(gemm_tf32_kernel<false>,
                         cudaFuncAttributeMaxDynamicSharedMemorySize, GEMM_SMEM_BYTES);
    cudaFuncSetAttribute(attn_kernel,
                         cudaFuncAttributeMaxDynamicSharedMemorySize, ATT_SMEM_BYTES);

    // pre-round inputs & weights to tf32
    round_one<<<(BATCH * SEQ_Q * E_DIM / 4 + 255) / 256, 256>>>(query, qr, BATCH * SEQ_Q * E_DIM / 4);
    round_one<<<(BATCH * SEQ_KV * E_DIM / 4 + 255) / 256, 256>>>(key_value, kvr, BATCH * SEQ_KV * E_DIM / 4);
    round_w<<<dim3(E_DIM * E_DIM / 4 / 256, 4), 256>>>(Wq, Wk, Wv, Wo, w);

    // projections
    gemm_tf32_kernel<true><<<dim3(BATCH * SEQ_Q / 128, E_DIM / 128), 256, GEMM_SMEM_BYTES>>>(
        qr, w, bq, Qp, SEQ_Q, 0.125f);
    gemm_tf32_kernel<true><<<dim3(BATCH * SEQ_KV / 128, E_DIM / 128), 256, GEMM_SMEM_BYTES>>>(
        kvr, w + (size_t)E_DIM * E_DIM, bk, Kp, SEQ_KV, 1.0f);
    gemm_tf32_kernel<true><<<dim3(BATCH * SEQ_KV / 128, E_DIM / 128), 256, GEMM_SMEM_BYTES>>>(
        kvr, w + 2 * (size_t)E_DIM * E_DIM, bv, Vp, SEQ_KV, 1.0f);

    // attention
    attn_kernel<<<dim3(SEQ_Q / 128, NHEAD, BATCH), 128, ATT_SMEM_BYTES>>>(kvmask);

    // output projection
    gemm_tf32_kernel<false><<<dim3(BATCH * SEQ_Q / 128, E_DIM / 128), 256, GEMM_SMEM_BYTES>>>(
        attn, w + 3 * (size_t)E_DIM * E_DIM, bo, proj, SEQ_Q, 1.0f);

    // residual + LN
    ln_kernel<<<BATCH * SEQ_Q, 256>>>(query, proj, gamma, beta, out);
}

// round 5
// speedup vs baseline: 1.4543x; 1.0475x over previous
#include <cuda_runtime.h>
#include <cstdint>
#include <cstddef>

#define E_DIM  1024
#define NHEAD  16
#define HDIM   64
#define BATCH  2
#define SEQ_Q  1024
#define SEQ_KV 4096
#define LN_EPS 1e-5f

// ---------------- scratch (no allocations allowed) ----------------
__device__ float g_Qp[(size_t)BATCH * NHEAD * SEQ_Q * HDIM];     // [B,H,SQ,D]  (tf32-rounded)
__device__ float g_Kp[(size_t)BATCH * NHEAD * SEQ_KV * HDIM];    // [B,H,SKV,D] (tf32-rounded)
__device__ float g_Vp[(size_t)BATCH * NHEAD * SEQ_KV * HDIM];    // [B,H,SKV,D] (tf32-rounded)
__device__ float g_attn[(size_t)BATCH * SEQ_Q * E_DIM];          // [B*SQ, E]   (tf32-rounded)
__device__ float g_proj[(size_t)BATCH * SEQ_Q * E_DIM];          // [B*SQ, E]
__device__ float g_qr [(size_t)BATCH * SEQ_Q * E_DIM];           // rounded query
__device__ float g_kvr[(size_t)BATCH * SEQ_KV * E_DIM];          // rounded key_value
__device__ float g_w  [(size_t)4 * E_DIM * E_DIM];               // rounded Wq,Wk,Wv,Wo

// ---------------- helpers ----------------
__device__ __forceinline__ float f2tff(float f) {
    unsigned u;
    asm("cvt.rna.tf32.f32 %0, %1;" : "=r"(u) : "f"(f));
    return __uint_as_float(u);
}

__device__ __forceinline__ void mma8(float* c, const unsigned* a, unsigned b0, unsigned b1) {
    asm volatile(
        "mma.sync.aligned.m16n8k8.row.col.f32.tf32.tf32.f32 "
        "{%0,%1,%2,%3}, {%4,%5,%6,%7}, {%8,%9}, {%0,%1,%2,%3};\n"
        : "+f"(c[0]), "+f"(c[1]), "+f"(c[2]), "+f"(c[3])
        : "r"(a[0]), "r"(a[1]), "r"(a[2]), "r"(a[3]), "r"(b0), "r"(b1));
}

__device__ __forceinline__ void ldsm4(unsigned* r, uint32_t addr) {
    asm volatile("ldmatrix.sync.aligned.m8n8.x4.shared.b16 {%0,%1,%2,%3}, [%4];"
                 : "=r"(r[0]), "=r"(r[1]), "=r"(r[2]), "=r"(r[3]) : "r"(addr));
}

__device__ __forceinline__ void cpasync16(const float* dst, const float* src) {
    uint32_t d = (uint32_t)__cvta_generic_to_shared(dst);
    asm volatile("cp.async.cg.shared.global [%0], [%1], 16;" :: "r"(d), "l"(src));
}
#define CP_COMMIT() asm volatile("cp.async.commit_group;" ::: "memory")
#define CP_WAIT(n)  asm volatile("cp.async.wait_group %0;" :: "n"(n) : "memory")

// ---------------- pre-round kernels (fp32 -> tf32-rounded fp32) ----------------
__global__ void __launch_bounds__(256) round_one(const float* __restrict__ in,
                                                 float* __restrict__ out, int n4) {
    int i = blockIdx.x * 256 + threadIdx.x;
    if (i < n4) {
        float4 v = ((const float4*)in)[i];
        float4 r;
        r.x = f2tff(v.x); r.y = f2tff(v.y); r.z = f2tff(v.z); r.w = f2tff(v.w);
        ((float4*)out)[i] = r;
    }
}

__global__ void __launch_bounds__(256) round_w(const float* __restrict__ a,
                                               const float* __restrict__ b,
                                               const float* __restrict__ c,
                                               const float* __restrict__ d,
                                               float* __restrict__ o) {
    const float* in = (blockIdx.y == 0) ? a : (blockIdx.y == 1) ? b : (blockIdx.y == 2) ? c : d;
    float* out = o + (size_t)blockIdx.y * E_DIM * E_DIM;
    int i = blockIdx.x * 256 + threadIdx.x;
    float4 v = ((const float4*)in)[i];
    float4 r;
    r.x = f2tff(v.x); r.y = f2tff(v.y); r.z = f2tff(v.z); r.w = f2tff(v.w);
    ((float4*)out)[i] = r;
}

// ---------------- GEMM: C[M,N] = A[M,K] * W[N,K]^T + bias (inputs tf32-rounded) ----------------
template <bool PERM>
__device__ __forceinline__ void storeC(float* __restrict__ C, int r, int c, float2 v, int S) {
    if (PERM) {
        int b = r / S;
        int s = r - b * S;
        int h = c >> 6;
        int d = c & 63;
        *(float2*)(C + (((size_t)b * NHEAD + h) * S + s) * HDIM + d) = v;
    } else {
        *(float2*)(C + (size_t)r * E_DIM + c) = v;
    }
}

// BM in {64,128}; BN=128, BK=32, 2-stage cp.async, ldmatrix fragment loads.
template <int BM, bool PERM>
__global__ void __launch_bounds__(256, 2) gemm_tf32_kernel(
    const float* __restrict__ A, const float* __restrict__ W,
    const float* __restrict__ bias, float* __restrict__ C,
    int S, float outScale)
{
    extern __shared__ float sm[];
    const int ASTG = BM * 36;         // floats per A stage
    const int BSTG = 128 * 36;        // floats per B stage
    float* As = sm;                   // [2][BM][36]
    float* Bs = sm + 2 * ASTG;        // [2][128][36]

    const int tid  = threadIdx.x;
    const int lane = tid & 31;
    const int warp = tid >> 5;
    const int lq   = lane >> 2;
    const int kq   = lane & 3;
    const int bm   = blockIdx.x * BM;
    const int bn   = blockIdx.y * 128;

    const int NT = (BM == 128) ? 8 : 4;                       // n-tiles per warp
    const int wm = (BM == 128) ? (warp & 3) * 32 : (warp & 1) * 32;
    const int wn = (BM == 128) ? (warp >> 2) * 64 : (warp >> 1) * 32;

    auto issue = [&](int kt, int s) {
#pragma unroll
        for (int p = 0; p < BM / 32; p++) {
            int i4  = p * 256 + tid;
            int row = i4 >> 3;
            int c4  = i4 & 7;
            cpasync16(As + s * ASTG + row * 36 + c4 * 4,
                      A + (size_t)(bm + row) * E_DIM + kt * 32 + c4 * 4);
        }
#pragma unroll
        for (int p = 0; p < 4; p++) {
            int i4  = p * 256 + tid;
            int row = i4 >> 3;
            int c4  = i4 & 7;
            cpasync16(Bs + s * BSTG + row * 36 + c4 * 4,
                      W + (size_t)(bn + row) * E_DIM + kt * 32 + c4 * 4);
        }
        CP_COMMIT();
    };

    float acc[2][8][4];
#pragma unroll
    for (int mt = 0; mt < 2; mt++)
#pragma unroll
        for (int nt = 0; nt < NT; nt++)
#pragma unroll
            for (int r = 0; r < 4; r++) acc[mt][nt][r] = 0.0f;

    // ldmatrix per-thread row/col offsets (in floats, added to stage base)
    // A fragment (m16k8): row = wm + mt*16 + (lane&15), col = k0 + (lane>>4)*4
    const int aOff0 = (wm + (lane & 15)) * 36 + ((lane >> 4) << 2);
    const int aOff1 = aOff0 + 16 * 36;
    // B fragment pair (two n8k8): row = wn + np*16 + (lane&7) + 8*(lane>=16), col = k0 + 4*((lane>>3)&1)
    const int bOffBase = (wn + (lane & 7) + ((lane & 16) >> 1)) * 36 + ((lane & 8) >> 1);

    issue(0, 0);
    issue(1, 1);

#pragma unroll 1
    for (int kt = 0; kt < 32; kt++) {
        if (kt + 1 < 32) { CP_WAIT(1); } else { CP_WAIT(0); }
        __syncthreads();
        uint32_t aB = (uint32_t)__cvta_generic_to_shared(As + (kt & 1) * ASTG);
        uint32_t bB = (uint32_t)__cvta_generic_to_shared(Bs + (kt & 1) * BSTG);

#pragma unroll
        for (int ks = 0; ks < 4; ks++) {
            const int k0 = ks * 8;
            unsigned af[2][4];
            ldsm4(af[0], aB + 4u * (aOff0 + k0));
            ldsm4(af[1], aB + 4u * (aOff1 + k0));
#pragma unroll
            for (int np = 0; np < NT / 2; np++) {
                unsigned bf[4];
                ldsm4(bf, bB + 4u * (bOffBase + np * 16 * 36 + k0));
                mma8(acc[0][2 * np],     af[0], bf[0], bf[1]);
                mma8(acc[1][2 * np],     af[1], bf[0], bf[1]);
                mma8(acc[0][2 * np + 1], af[0], bf[2], bf[3]);
                mma8(acc[1][2 * np + 1], af[1], bf[2], bf[3]);
            }
        }
        __syncthreads();
        if (kt + 2 < 32) issue(kt + 2, kt & 1);
    }

    // epilogue
#pragma unroll
    for (int mt = 0; mt < 2; mt++) {
        int rA = bm + wm + mt * 16 + lq;
#pragma unroll
        for (int nt = 0; nt < NT; nt++) {
            int c0 = bn + wn + nt * 8 + 2 * kq;
            float b0 = bias[c0], b1 = bias[c0 + 1];
            float v0 = (acc[mt][nt][0] + b0) * outScale;
            float v1 = (acc[mt][nt][1] + b1) * outScale;
            float v2 = (acc[mt][nt][2] + b0) * outScale;
            float v3 = (acc[mt][nt][3] + b1) * outScale;
            if (PERM) { v0 = f2tff(v0); v1 = f2tff(v1); v2 = f2tff(v2); v3 = f2tff(v3); }
            storeC<PERM>(C, rA, c0, make_float2(v0, v1), S);
            storeC<PERM>(C, rA + 8, c0, make_float2(v2, v3), S);
        }
    }
}

// ---------------- Flash attention ----------------
// grid (SQ/128, H, B), 128 threads; warp = 32 q-rows (2 row-blocks of 16).
// cp.async double-buffered K/V, ldmatrix K fragments, shuffle-based P fragments.
#define QSTR 68
#define KSTR 68
#define VSTR 72
#define KTILE_F (64 * KSTR)
#define VTILE_F (64 * VSTR)
#define QOFF 0
#define KOFF (128 * QSTR)
#define VOFF (KOFF + 2 * KTILE_F)
#define MOFF (VOFF + 2 * VTILE_F)
#define ATT_SMEM_BYTES ((MOFF + 128) * 4)

__global__ void __launch_bounds__(128) attn_kernel(const int* __restrict__ kvmask)
{
    extern __shared__ float sm[];

    const int tid  = threadIdx.x;
    const int lane = tid & 31;
    const int warp = tid >> 5;
    const int lq   = lane >> 2;
    const int kq   = lane & 3;
    const int qt = blockIdx.x, h = blockIdx.y, b = blockIdx.z;

    const float* Qg = g_Qp + (((size_t)b * NHEAD + h) * SEQ_Q + qt * 128) * HDIM;
    const float* Kg = g_Kp + ((size_t)b * NHEAD + h) * SEQ_KV * HDIM;
    const float* Vg = g_Vp + ((size_t)b * NHEAD + h) * SEQ_KV * HDIM;
    const int*   mg = kvmask + (size_t)b * SEQ_KV;

    // Q tile -> smem (one-time)
#pragma unroll
    for (int p = 0; p < 16; p++) {
        int i4  = p * 128 + tid;
        int row = i4 >> 4;
        int c4  = i4 & 15;
        cpasync16(sm + QOFF + row * QSTR + c4 * 4, Qg + row * HDIM + c4 * 4);
    }
    CP_COMMIT();
    CP_WAIT(0);
    __syncthreads();

    const int r0 = warp * 32;
    unsigned qf[2][8][4];
#pragma unroll
    for (int rb = 0; rb < 2; rb++)
#pragma unroll
        for (int ks = 0; ks < 8; ks++) {
            int rr = r0 + rb * 16;
            qf[rb][ks][0] = __float_as_uint(sm[QOFF + (rr + lq) * QSTR + ks * 8 + kq]);
            qf[rb][ks][1] = __float_as_uint(sm[QOFF + (rr + 8 + lq) * QSTR + ks * 8 + kq]);
            qf[rb][ks][2] = __float_as_uint(sm[QOFF + (rr + lq) * QSTR + ks * 8 + 4 + kq]);
            qf[rb][ks][3] = __float_as_uint(sm[QOFF + (rr + 8 + lq) * QSTR + ks * 8 + 4 + kq]);
        }
    __syncthreads();

    auto issue = [&](int kt, int s) {
        const float* kp = Kg + (size_t)kt * 64 * HDIM;
        const float* vp = Vg + (size_t)kt * 64 * HDIM;
#pragma unroll
        for (int p = 0; p < 8; p++) {
            int i4  = p * 128 + tid;
            int row = i4 >> 4;
            int c4  = i4 & 15;
            cpasync16(sm + KOFF + s * KTILE_F + row * KSTR + c4 * 4, kp + row * HDIM + c4 * 4);
            cpasync16(sm + VOFF + s * VTILE_F + row * VSTR + c4 * 4, vp + row * HDIM + c4 * 4);
        }
        if (tid < 64) sm[MOFF + s * 64 + tid] = mg[kt * 64 + tid] ? 0.0f : -3.0e38f;
        CP_COMMIT();
    };

    float o[2][8][4];
#pragma unroll
    for (int rb = 0; rb < 2; rb++)
#pragma unroll
        for (int nt = 0; nt < 8; nt++)
#pragma unroll
            for (int r = 0; r < 4; r++) o[rb][nt][r] = 0.0f;

    float mA[2] = {-1e30f, -1e30f}, mB[2] = {-1e30f, -1e30f};
    float lA[2] = {0.0f, 0.0f},     lB[2] = {0.0f, 0.0f};

    issue(0, 0);
    issue(1, 1);

    const int  srcA = (lane & ~3) | (kq >> 1);
    const int  srcB = srcA + 2;
    const bool par  = (kq & 1);
    // ldmatrix offset for K fragments: row = np*16 + (lane&7) + 8*(lane>=16), col = k0 + 4*((lane>>3)&1)
    const int kOffBase = ((lane & 7) + ((lane & 16) >> 1)) * KSTR + ((lane & 8) >> 1);

#pragma unroll 1
    for (int kt = 0; kt < SEQ_KV / 64; kt++) {
        if (kt + 1 < SEQ_KV / 64) { CP_WAIT(1); } else { CP_WAIT(0); }
        __syncthreads();
        const int s = kt & 1;
        const float* Vst = sm + VOFF + s * VTILE_F;
        const float* msk = sm + MOFF + s * 64;
        uint32_t kB = (uint32_t)__cvta_generic_to_shared(sm + KOFF + s * KTILE_F);

        // S = Q K^T
        float sacc[2][8][4];
#pragma unroll
        for (int rb = 0; rb < 2; rb++)
#pragma unroll
            for (int nt = 0; nt < 8; nt++)
#pragma unroll
                for (int r = 0; r < 4; r++) sacc[rb][nt][r] = 0.0f;

#pragma unroll
        for (int ks = 0; ks < 8; ks++) {
            const int k0 = ks * 8;
#pragma unroll
            for (int np = 0; np < 4; np++) {
                unsigned kf[4];
                ldsm4(kf, kB + 4u * (kOffBase + np * 16 * KSTR + k0));
                mma8(sacc[0][2 * np],     qf[0][ks], kf[0], kf[1]);
                mma8(sacc[1][2 * np],     qf[1][ks], kf[0], kf[1]);
                mma8(sacc[0][2 * np + 1], qf[0][ks], kf[2], kf[3]);
                mma8(sacc[1][2 * np + 1], qf[1][ks], kf[2], kf[3]);
            }
        }

        // mask + row max
        float tm[2][2] = {{-3.0e38f, -3.0e38f}, {-3.0e38f, -3.0e38f}};
#pragma unroll
        for (int nt = 0; nt < 8; nt++) {
            float m0 = msk[nt * 8 + 2 * kq];
            float m1 = msk[nt * 8 + 2 * kq + 1];
#pragma unroll
            for (int rb = 0; rb < 2; rb++) {
                sacc[rb][nt][0] += m0; sacc[rb][nt][1] += m1;
                sacc[rb][nt][2] += m0; sacc[rb][nt][3] += m1;
                tm[rb][0] = fmaxf(tm[rb][0], fmaxf(sacc[rb][nt][0], sacc[rb][nt][1]));
                tm[rb][1] = fmaxf(tm[rb][1], fmaxf(sacc[rb][nt][2], sacc[rb][nt][3]));
            }
        }
#pragma unroll
        for (int rb = 0; rb < 2; rb++)
#pragma unroll
            for (int j = 0; j < 2; j++) {
                tm[rb][j] = fmaxf(tm[rb][j], __shfl_xor_sync(0xffffffffu, tm[rb][j], 1));
                tm[rb][j] = fmaxf(tm[rb][j], __shfl_xor_sync(0xffffffffu, tm[rb][j], 2));
            }

        float aA[2], aB[2];
#pragma unroll
        for (int rb = 0; rb < 2; rb++) {
            float mnA = fmaxf(mA[rb], tm[rb][0]);
            float mnB = fmaxf(mB[rb], tm[rb][1]);
            aA[rb] = __expf(mA[rb] - mnA);
            aB[rb] = __expf(mB[rb] - mnB);
            mA[rb] = mnA; mB[rb] = mnB;
        }

        float sums[2][2] = {{0.0f, 0.0f}, {0.0f, 0.0f}};
#pragma unroll
        for (int nt = 0; nt < 8; nt++) {
#pragma unroll
            for (int rb = 0; rb < 2; rb++) {
                float p0 = f2tff(__expf(sacc[rb][nt][0] - mA[rb]));
                float p1 = f2tff(__expf(sacc[rb][nt][1] - mA[rb]));
                float p2 = f2tff(__expf(sacc[rb][nt][2] - mB[rb]));
                float p3 = f2tff(__expf(sacc[rb][nt][3] - mB[rb]));
                sums[rb][0] += p0 + p1;
                sums[rb][1] += p2 + p3;
                sacc[rb][nt][0] = p0; sacc[rb][nt][1] = p1;
                sacc[rb][nt][2] = p2; sacc[rb][nt][3] = p3;
                o[rb][nt][0] *= aA[rb]; o[rb][nt][1] *= aA[rb];
                o[rb][nt][2] *= aB[rb]; o[rb][nt][3] *= aB[rb];
            }
        }
#pragma unroll
        for (int rb = 0; rb < 2; rb++) {
#pragma unroll
            for (int j = 0; j < 2; j++) {
                sums[rb][j] += __shfl_xor_sync(0xffffffffu, sums[rb][j], 1);
                sums[rb][j] += __shfl_xor_sync(0xffffffffu, sums[rb][j], 2);
            }
            lA[rb] = lA[rb] * aA[rb] + sums[rb][0];
            lB[rb] = lB[rb] * aB[rb] + sums[rb][1];
        }

        // O += P V  (P fragments via shuffle from C-layout)
#pragma unroll
        for (int ks = 0; ks < 8; ks++) {
            unsigned pf[2][4];
#pragma unroll
            for (int rb = 0; rb < 2; rb++) {
                float u0 = __shfl_sync(0xffffffffu, sacc[rb][ks][0], srcA);
                float u1 = __shfl_sync(0xffffffffu, sacc[rb][ks][1], srcA);
                float u2 = __shfl_sync(0xffffffffu, sacc[rb][ks][2], srcA);
                float u3 = __shfl_sync(0xffffffffu, sacc[rb][ks][3], srcA);
                float w0 = __shfl_sync(0xffffffffu, sacc[rb][ks][0], srcB);
                float w1 = __shfl_sync(0xffffffffu, sacc[rb][ks][1], srcB);
                float w2 = __shfl_sync(0xffffffffu, sacc[rb][ks][2], srcB);
                float w3 = __shfl_sync(0xffffffffu, sacc[rb][ks][3], srcB);
                pf[rb][0] = __float_as_uint(par ? u1 : u0);
                pf[rb][1] = __float_as_uint(par ? u3 : u2);
                pf[rb][2] = __float_as_uint(par ? w1 : w0);
                pf[rb][3] = __float_as_uint(par ? w3 : w2);
            }
#pragma unroll
            for (int nt = 0; nt < 8; nt++) {
                unsigned b0 = __float_as_uint(Vst[(ks * 8 + kq) * VSTR + nt * 8 + lq]);
                unsigned b1 = __float_as_uint(Vst[(ks * 8 + 4 + kq) * VSTR + nt * 8 + lq]);
                mma8(o[0][nt], pf[0], b0, b1);
                mma8(o[1][nt], pf[1], b0, b1);
            }
        }
        __syncthreads();
        if (kt + 2 < SEQ_KV / 64) issue(kt + 2, s);
    }

    // normalize + round + write [B*SQ, E]
    float* outBase = g_attn + (size_t)b * SEQ_Q * E_DIM;
#pragma unroll
    for (int rb = 0; rb < 2; rb++) {
        float rA = 1.0f / lA[rb], rB = 1.0f / lB[rb];
        int qA = qt * 128 + r0 + rb * 16 + lq;
#pragma unroll
        for (int nt = 0; nt < 8; nt++) {
            int c = h * HDIM + nt * 8 + 2 * kq;
            *(float2*)(outBase + (size_t)qA * E_DIM + c) =
                make_float2(f2tff(o[rb][nt][0] * rA), f2tff(o[rb][nt][1] * rA));
            *(float2*)(outBase + (size_t)(qA + 8) * E_DIM + c) =
                make_float2(f2tff(o[rb][nt][2] * rB), f2tff(o[rb][nt][3] * rB));
        }
    }
}

// ---------------- residual + LayerNorm ----------------
__global__ void __launch_bounds__(256) ln_kernel(
    const float* __restrict__ query, const float* __restrict__ proj,
    const float* __restrict__ gamma, const float* __restrict__ beta,
    float* __restrict__ out)
{
    __shared__ float rs[8], rs2[8];
    const int row = blockIdx.x, tid = threadIdx.x;
    const int lane = tid & 31, warp = tid >> 5;
    const size_t base = (size_t)row * E_DIM + tid * 4;

    float4 q = *(const float4*)(query + base);
    float4 p = *(const float4*)(proj + base);
    float x0 = q.x + p.x, x1 = q.y + p.y, x2 = q.z + p.z, x3 = q.w + p.w;
    float s  = x0 + x1 + x2 + x3;
    float s2 = x0 * x0 + x1 * x1 + x2 * x2 + x3 * x3;
#pragma unroll
    for (int off = 16; off; off >>= 1) {
        s  += __shfl_xor_sync(0xffffffffu, s, off);
        s2 += __shfl_xor_sync(0xffffffffu, s2, off);
    }
    if (lane == 0) { rs[warp] = s; rs2[warp] = s2; }
    __syncthreads();
    s = 0.0f; s2 = 0.0f;
#pragma unroll
    for (int i = 0; i < 8; i++) { s += rs[i]; s2 += rs2[i]; }

    float mean = s * (1.0f / E_DIM);
    float var  = s2 * (1.0f / E_DIM) - mean * mean;
    float rstd = rsqrtf(var + LN_EPS);

    float4 g  = *(const float4*)(gamma + tid * 4);
    float4 bb = *(const float4*)(beta + tid * 4);
    float4 r;
    r.x = (x0 - mean) * rstd * g.x + bb.x;
    r.y = (x1 - mean) * rstd * g.y + bb.y;
    r.z = (x2 - mean) * rstd * g.z + bb.z;
    r.w = (x3 - mean) * rstd * g.w + bb.w;
    *(float4*)(out + base) = r;
}

// ---------------- launch ----------------
extern "C" void kernel_launch(void* const* d_in, const int* in_sizes, int n_in,
                              void* d_out, int out_size)
{
    const float* query     = (const float*)d_in[0];
    const float* key_value = (const float*)d_in[1];
    const int*   kvmask    = (const int*)d_in[2];
    const float* Wq = (const float*)d_in[3];
    const float* bq = (const float*)d_in[4];
    const float* Wk = (const float*)d_in[5];
    const float* bk = (const float*)d_in[6];
    const float* Wv = (const float*)d_in[7];
    const float* bv = (const float*)d_in[8];
    const float* Wo = (const float*)d_in[9];
    const float* bo = (const float*)d_in[10];
    const float* gamma = (const float*)d_in[11];
    const float* beta  = (const float*)d_in[12];
    float* out = (float*)d_out;

    float *Qp, *Kp, *Vp, *attn, *proj, *qr, *kvr, *w;
    cudaGetSymbolAddress((void**)&Qp, g_Qp);
    cudaGetSymbolAddress((void**)&Kp, g_Kp);
    cudaGetSymbolAddress((void**)&Vp, g_Vp);
    cudaGetSymbolAddress((void**)&attn, g_attn);
    cudaGetSymbolAddress((void**)&proj, g_proj);
    cudaGetSymbolAddress((void**)&qr, g_qr);
    cudaGetSymbolAddress((void**)&kvr, g_kvr);
    cudaGetSymbolAddress((void**)&w, g_w);

    const int SMEM128 = 2 * (128 + 128) * 36 * 4;   // 73728 B
    const int SMEM64  = 2 * (64 + 128) * 36 * 4;    // 55296 B
    cudaFuncSetAttribute(gemm_tf32_kernel<128, true>,
                         cudaFuncAttributeMaxDynamicSharedMemorySize, SMEM128);
    cudaFuncSetAttribute(gemm_tf32_kernel<64, true>,
                         cudaFuncAttributeMaxDynamicSharedMemorySize, SMEM64);
    cudaFuncSetAttribute(gemm_tf32_kernel<64, false>,
                         cudaFuncAttributeMaxDynamicSharedMemorySize, SMEM64);
    cudaFuncSetAttribute(attn_kernel,
                         cudaFuncAttributeMaxDynamicSharedMemorySize, ATT_SMEM_BYTES);

    // pre-round inputs & weights to tf32
    round_one<<<(BATCH * SEQ_Q * E_DIM / 4 + 255) / 256, 256>>>(query, qr, BATCH * SEQ_Q * E_DIM / 4);
    round_one<<<(BATCH * SEQ_KV * E_DIM / 4 + 255) / 256, 256>>>(key_value, kvr, BATCH * SEQ_KV * E_DIM / 4);
    round_w<<<dim3(E_DIM * E_DIM / 4 / 256, 4), 256>>>(Wq, Wk, Wv, Wo, w);

    // projections: Q uses BM=64 (fills grid), K/V use BM=128
    gemm_tf32_kernel<64, true><<<dim3(BATCH * SEQ_Q / 64, E_DIM / 128), 256, SMEM64>>>(
        qr, w, bq, Qp, SEQ_Q, 0.125f);
    gemm_tf32_kernel<128, true><<<dim3(BATCH * SEQ_KV / 128, E_DIM / 128), 256, SMEM128>>>(
        kvr, w + (size_t)E_DIM * E_DIM, bk, Kp, SEQ_KV, 1.0f);
    gemm_tf32_kernel<128, true><<<dim3(BATCH * SEQ_KV / 128, E_DIM / 128), 256, SMEM128>>>(
        kvr, w + 2 * (size_t)E_DIM * E_DIM, bv, Vp, SEQ_KV, 1.0f);

    // attention
    attn_kernel<<<dim3(SEQ_Q / 128, NHEAD, BATCH), 128, ATT_SMEM_BYTES>>>(kvmask);

    // output projection (BM=64 to fill grid)
    gemm_tf32_kernel<64, false><<<dim3(BATCH * SEQ_Q / 64, E_DIM / 128), 256, SMEM64>>>(
        attn, w + 3 * (size_t)E_DIM * E_DIM, bo, proj, SEQ_Q, 1.0f);

    // residual + LN
    ln_kernel<<<BATCH * SEQ_Q, 256>>>(query, proj, gamma, beta, out);
}